// round 3
// baseline (speedup 1.0000x reference)
#include <cuda_runtime.h>
#include <cuda_bf16.h>

// Problem shapes (fixed by the dataset): B=4, N=512, C=64.
#define B_DIM 4
#define N_DIM 512
#define C_DIM 64
#define NROWS (B_DIM * N_DIM)   // 2048

// sqrt(log2(e)) — x is pre-scaled by this so exp(xi*xj) == ex2(xi'*xj').
#define SQRT_LOG2E 1.2011224087864498f

// Scratch for the intermediate x' = LN(ReLU(h@W^T + b)) * sqrt(log2 e).
__device__ float g_x[NROWS * C_DIM];

__device__ __forceinline__ float ex2_approx(float x) {
    float y;
    asm("ex2.approx.ftz.f32 %0, %1;" : "=f"(y) : "f"(x));
    return y;
}
__device__ __forceinline__ float rcp_approx(float x) {
    float y;
    asm("rcp.approx.ftz.f32 %0, %1;" : "=f"(y) : "f"(x));
    return y;
}

// ---------------------------------------------------------------------------
// Kernel 1: x' = (LayerNorm(ReLU(h @ W^T + b)) * gamma + beta) * sqrt(log2 e)
// 16 rows per 1024-thread block (128 blocks = one wave). W staged in SMEM
// with stride-65 padding (conflict-free per-thread sequential reads).
// ---------------------------------------------------------------------------
__global__ __launch_bounds__(1024) void mlp_ln_kernel(
    const float* __restrict__ h, const float* __restrict__ W,
    const float* __restrict__ bias, const float* __restrict__ gamma,
    const float* __restrict__ beta)
{
    __shared__ float Ws[C_DIM * 65];
    __shared__ float hs[16][C_DIM];
    __shared__ float red[16][2][2];   // [row][warp-half][sum, sumsq]

    const int tid = threadIdx.x;
    const int r   = tid >> 6;        // 0..15 row within block
    const int d   = tid & 63;        // output channel
    const int row = blockIdx.x * 16 + r;

    // Stage W (4096 floats) coalesced, padded layout Ws[d*65 + c].
    #pragma unroll
    for (int i = 0; i < 4; i++) {
        int idx = tid + i * 1024;
        Ws[(idx >> 6) * 65 + (idx & 63)] = W[idx];
    }
    hs[r][d] = h[row * C_DIM + d];
    __syncthreads();

    float acc = bias[d];
    #pragma unroll
    for (int c = 0; c < C_DIM; c++)
        acc = fmaf(hs[r][c], Ws[d * 65 + c], acc);

    float v = fmaxf(acc, 0.0f);

    // LayerNorm over the 64 channels of this row (= 2 warps).
    float s  = v;
    float s2 = v * v;
    #pragma unroll
    for (int off = 16; off; off >>= 1) {
        s  += __shfl_xor_sync(0xffffffffu, s,  off);
        s2 += __shfl_xor_sync(0xffffffffu, s2, off);
    }
    const int half = d >> 5;
    if ((d & 31) == 0) { red[r][half][0] = s; red[r][half][1] = s2; }
    __syncthreads();

    const float S   = red[r][0][0] + red[r][1][0];
    const float S2  = red[r][0][1] + red[r][1][1];
    const float mu  = S * (1.0f / 64.0f);
    const float var = S2 * (1.0f / 64.0f) - mu * mu;
    const float inv_std = rsqrtf(var + 1e-5f);

    g_x[row * C_DIM + d] =
        ((v - mu) * inv_std * gamma[d] + beta[d]) * SQRT_LOG2E;
}

// ---------------------------------------------------------------------------
// Kernel 2: out[b,i,j,c] = softmax_c( x[b,i,c] * x[b,j,c] )
//
// 16x16 (i,j) tile per 256-thread block. Each 8-lane group owns one pair:
// lane (p,q) with p=lane>>3, q=lane&7 handles channel float4s q and q+8 of
// pair (li, lj). 4 pairs per warp inner-iter.
//   li = 2*warp + h (outer loop, 2),  lj = 4*kk + p (inner unroll, 4)
// Outer/inner split keeps live ranges small -> <=42 regs at
// __launch_bounds__(256, 6): 6 blocks/SM = 48 warps (75% occupancy), which
// is what keeps enough STG.128s in flight to drain at the HBM write ceiling.
// LDS.128 quarter-warp phases align with p-groups: conflict-free.
// Sum reduce = 3 xor-shuffles. exp == raw ex2 (inputs pre-scaled by k1).
// Streaming stores (__stcs): output is write-only, evict-first in L2.
// ---------------------------------------------------------------------------
#define TI 16
#define TJ 16

__global__ __launch_bounds__(256, 6) void pair_softmax_kernel(float* __restrict__ out)
{
    __shared__ float4 xi[TI * 16];   // 16 rows x 16 float4 = 4 KB
    __shared__ float4 xj[TJ * 16];

    const int bb = blockIdx.z;
    const int i0 = blockIdx.y * TI;
    const int j0 = blockIdx.x * TJ;
    const int tid = threadIdx.x;

    // Stage x tiles: each thread loads one float4 per tile.
    const float4* xg = (const float4*)g_x;   // row r = xg[r*16 + q]
    {
        const int r = tid >> 4;
        const int q = tid & 15;
        xi[tid] = xg[(size_t)(bb * N_DIM + i0 + r) * 16 + q];
        xj[tid] = xg[(size_t)(bb * N_DIM + j0 + r) * 16 + q];
    }
    __syncthreads();

    const int warp = tid >> 5;
    const int lane = tid & 31;
    const int p    = lane >> 3;   // which of 4 pairs this lane serves
    const int q    = lane & 7;    // channel float4 slot (and slot q+8)

    float4* out4 = (float4*)out;

    #pragma unroll
    for (int hh = 0; hh < 2; hh++) {
        const int li = 2 * warp + hh;
        const float4* xrow = &xi[li * 16];
        const float4 a0 = xrow[q];
        const float4 a1 = xrow[q + 8];

        const size_t base0 =
            ((size_t)(bb * N_DIM + i0 + li) * N_DIM + (j0 + p)) * 16 + q;

        #pragma unroll
        for (int kk = 0; kk < 4; kk++) {
            const float4 b0 = xj[(4 * kk + p) * 16 + q];
            const float4 b1 = xj[(4 * kk + p) * 16 + q + 8];

            float e0 = ex2_approx(a0.x * b0.x);
            float e1 = ex2_approx(a0.y * b0.y);
            float e2 = ex2_approx(a0.z * b0.z);
            float e3 = ex2_approx(a0.w * b0.w);
            float e4 = ex2_approx(a1.x * b1.x);
            float e5 = ex2_approx(a1.y * b1.y);
            float e6 = ex2_approx(a1.z * b1.z);
            float e7 = ex2_approx(a1.w * b1.w);

            float s = ((e0 + e1) + (e2 + e3)) + ((e4 + e5) + (e6 + e7));
            s += __shfl_xor_sync(0xffffffffu, s, 4);
            s += __shfl_xor_sync(0xffffffffu, s, 2);
            s += __shfl_xor_sync(0xffffffffu, s, 1);

            const float inv = rcp_approx(s);

            float4 o0, o1;
            o0.x = e0 * inv; o0.y = e1 * inv; o0.z = e2 * inv; o0.w = e3 * inv;
            o1.x = e4 * inv; o1.y = e5 * inv; o1.z = e6 * inv; o1.w = e7 * inv;

            const size_t base = base0 + (size_t)kk * 64;
            __stcs(&out4[base],     o0);
            __stcs(&out4[base + 8], o1);
        }
    }
}

// ---------------------------------------------------------------------------
extern "C" void kernel_launch(void* const* d_in, const int* in_sizes, int n_in,
                              void* d_out, int out_size)
{
    const float* h     = (const float*)d_in[0];
    const float* W     = (const float*)d_in[1];
    const float* bias  = (const float*)d_in[2];
    const float* gamma = (const float*)d_in[3];
    const float* beta  = (const float*)d_in[4];

    mlp_ln_kernel<<<NROWS / 16, 1024>>>(h, W, bias, gamma, beta);

    dim3 grid(N_DIM / TJ, N_DIM / TI, B_DIM);   // (32, 32, 4)
    pair_softmax_kernel<<<grid, 256>>>((float*)d_out);
}

// round 4
// speedup vs baseline: 1.0114x; 1.0114x over previous
#include <cuda_runtime.h>
#include <cuda_bf16.h>

// Problem shapes (fixed by the dataset): B=4, N=512, C=64.
#define B_DIM 4
#define N_DIM 512
#define C_DIM 64
#define NROWS (B_DIM * N_DIM)   // 2048

// sqrt(log2(e)) — x is pre-scaled by this so exp(xi*xj) == ex2(xi'*xj').
#define SQRT_LOG2E 1.2011224087864498f

// Scratch for the intermediate x' = LN(ReLU(h@W^T + b)) * sqrt(log2 e).
__device__ float g_x[NROWS * C_DIM];

__device__ __forceinline__ float ex2_approx(float x) {
    float y;
    asm("ex2.approx.ftz.f32 %0, %1;" : "=f"(y) : "f"(x));
    return y;
}
__device__ __forceinline__ float rcp_approx(float x) {
    float y;
    asm("rcp.approx.ftz.f32 %0, %1;" : "=f"(y) : "f"(x));
    return y;
}

// ---------------------------------------------------------------------------
// Kernel 1: x' = (LayerNorm(ReLU(h @ W^T + b)) * gamma + beta) * sqrt(log2 e)
// 16 rows per 1024-thread block (128 blocks = one wave). W staged in SMEM
// with stride-65 padding (conflict-free per-thread sequential reads).
// ---------------------------------------------------------------------------
__global__ __launch_bounds__(1024) void mlp_ln_kernel(
    const float* __restrict__ h, const float* __restrict__ W,
    const float* __restrict__ bias, const float* __restrict__ gamma,
    const float* __restrict__ beta)
{
    __shared__ float Ws[C_DIM * 65];
    __shared__ float hs[16][C_DIM];
    __shared__ float red[16][2][2];   // [row][warp-half][sum, sumsq]

    const int tid = threadIdx.x;
    const int r   = tid >> 6;        // 0..15 row within block
    const int d   = tid & 63;        // output channel
    const int row = blockIdx.x * 16 + r;

    // Stage W (4096 floats) coalesced, padded layout Ws[d*65 + c].
    #pragma unroll
    for (int i = 0; i < 4; i++) {
        int idx = tid + i * 1024;
        Ws[(idx >> 6) * 65 + (idx & 63)] = W[idx];
    }
    hs[r][d] = h[row * C_DIM + d];
    __syncthreads();

    float acc = bias[d];
    #pragma unroll
    for (int c = 0; c < C_DIM; c++)
        acc = fmaf(hs[r][c], Ws[d * 65 + c], acc);

    float v = fmaxf(acc, 0.0f);

    // LayerNorm over the 64 channels of this row (= 2 warps).
    float s  = v;
    float s2 = v * v;
    #pragma unroll
    for (int off = 16; off; off >>= 1) {
        s  += __shfl_xor_sync(0xffffffffu, s,  off);
        s2 += __shfl_xor_sync(0xffffffffu, s2, off);
    }
    const int half = d >> 5;
    if ((d & 31) == 0) { red[r][half][0] = s; red[r][half][1] = s2; }
    __syncthreads();

    const float S   = red[r][0][0] + red[r][1][0];
    const float S2  = red[r][0][1] + red[r][1][1];
    const float mu  = S * (1.0f / 64.0f);
    const float var = S2 * (1.0f / 64.0f) - mu * mu;
    const float inv_std = rsqrtf(var + 1e-5f);

    g_x[row * C_DIM + d] =
        ((v - mu) * inv_std * gamma[d] + beta[d]) * SQRT_LOG2E;
}

// ---------------------------------------------------------------------------
// Kernel 2: out[b,i,j,c] = softmax_c( x[b,i,c] * x[b,j,c] )
//
// Exact R2-winning configuration (39.8us): 16x16 tile, 8-lane group per pair,
// full 8-iter unroll (deep per-warp store ILP beats occupancy here — proven
// by R3's regression when reg-clamped). Launched with PDL: blocks come up
// while kernel 1 drains; griddepcontrol.wait gates the g_x reads.
// ---------------------------------------------------------------------------
#define TI 16
#define TJ 16

__global__ __launch_bounds__(256) void pair_softmax_kernel(float* __restrict__ out)
{
    __shared__ float4 xi[TI * 16];   // 16 rows x 16 float4 = 4 KB
    __shared__ float4 xj[TJ * 16];

    const int bb = blockIdx.z;
    const int i0 = blockIdx.y * TI;
    const int j0 = blockIdx.x * TJ;
    const int tid = threadIdx.x;

    // PDL: wait for kernel 1's completion signal before touching g_x.
    asm volatile("griddepcontrol.wait;" ::: "memory");

    // Stage x tiles: each thread loads one float4 per tile.
    const float4* xg = (const float4*)g_x;   // row r = xg[r*16 + q]
    {
        const int r = tid >> 4;
        const int q = tid & 15;
        xi[tid] = xg[(size_t)(bb * N_DIM + i0 + r) * 16 + q];
        xj[tid] = xg[(size_t)(bb * N_DIM + j0 + r) * 16 + q];
    }
    __syncthreads();

    const int warp = tid >> 5;
    const int lane = tid & 31;
    const int p    = lane >> 3;   // which of 4 pairs this lane serves
    const int q    = lane & 7;    // channel float4 slot (and slot q+8)

    float4* out4 = (float4*)out;

    // xi rows for this warp (loop-invariant within each half).
    const float4* xi_lo = &xi[(2 * warp)     * 16];
    const float4* xi_hi = &xi[(2 * warp + 1) * 16];

    const size_t base_lo =
        ((size_t)(bb * N_DIM + i0 + 2 * warp) * N_DIM + (j0 + p)) * 16 + q;
    const size_t base_hi = base_lo + (size_t)N_DIM * 16;

    #pragma unroll
    for (int k = 0; k < 8; k++) {
        const int kk = k & 3;
        const float4* xrow = (k < 4) ? xi_lo : xi_hi;

        const float4 a0 = xrow[q];
        const float4 a1 = xrow[q + 8];
        const float4 b0 = xj[(4 * kk + p) * 16 + q];
        const float4 b1 = xj[(4 * kk + p) * 16 + q + 8];

        float e0 = ex2_approx(a0.x * b0.x);
        float e1 = ex2_approx(a0.y * b0.y);
        float e2 = ex2_approx(a0.z * b0.z);
        float e3 = ex2_approx(a0.w * b0.w);
        float e4 = ex2_approx(a1.x * b1.x);
        float e5 = ex2_approx(a1.y * b1.y);
        float e6 = ex2_approx(a1.z * b1.z);
        float e7 = ex2_approx(a1.w * b1.w);

        float s = ((e0 + e1) + (e2 + e3)) + ((e4 + e5) + (e6 + e7));
        s += __shfl_xor_sync(0xffffffffu, s, 4);
        s += __shfl_xor_sync(0xffffffffu, s, 2);
        s += __shfl_xor_sync(0xffffffffu, s, 1);

        const float inv = rcp_approx(s);

        float4 o0, o1;
        o0.x = e0 * inv; o0.y = e1 * inv; o0.z = e2 * inv; o0.w = e3 * inv;
        o1.x = e4 * inv; o1.y = e5 * inv; o1.z = e6 * inv; o1.w = e7 * inv;

        const size_t base = ((k < 4) ? base_lo : base_hi) + (size_t)kk * 64;
        __stcs(&out4[base],     o0);
        __stcs(&out4[base + 8], o1);
    }
}

// ---------------------------------------------------------------------------
extern "C" void kernel_launch(void* const* d_in, const int* in_sizes, int n_in,
                              void* d_out, int out_size)
{
    const float* h     = (const float*)d_in[0];
    const float* W     = (const float*)d_in[1];
    const float* bias  = (const float*)d_in[2];
    const float* gamma = (const float*)d_in[3];
    const float* beta  = (const float*)d_in[4];

    mlp_ln_kernel<<<NROWS / 16, 1024>>>(h, W, bias, gamma, beta);

    // Kernel 2 with programmatic dependent launch: overlap its launch/setup
    // with kernel 1's execution; griddepcontrol.wait inside the kernel
    // provides the data dependency on g_x.
    cudaLaunchConfig_t cfg = {};
    cfg.gridDim  = dim3(N_DIM / TJ, N_DIM / TI, B_DIM);   // (32, 32, 4)
    cfg.blockDim = dim3(256, 1, 1);
    cfg.dynamicSmemBytes = 0;
    cfg.stream = 0;

    cudaLaunchAttribute attrs[1];
    attrs[0].id = cudaLaunchAttributeProgrammaticStreamSerialization;
    attrs[0].val.programmaticStreamSerializationAllowed = 1;
    cfg.attrs = attrs;
    cfg.numAttrs = 1;

    cudaLaunchKernelEx(&cfg, pair_softmax_kernel, (float*)d_out);
}

// round 5
// speedup vs baseline: 1.0471x; 1.0353x over previous
#include <cuda_runtime.h>
#include <cuda_bf16.h>

// Problem shapes (fixed by the dataset): B=4, N=512, C=64.
#define B_DIM 4
#define N_DIM 512
#define C_DIM 64
#define NROWS (B_DIM * N_DIM)   // 2048

// sqrt(log2(e)) — x is pre-scaled by this so exp(xi*xj) == ex2(xi'*xj').
#define SQRT_LOG2E 1.2011224087864498f

// Scratch for the intermediate x' = LN(ReLU(h@W^T + b)) * sqrt(log2 e).
__device__ float g_x[NROWS * C_DIM];

__device__ __forceinline__ float ex2_approx(float x) {
    float y;
    asm("ex2.approx.ftz.f32 %0, %1;" : "=f"(y) : "f"(x));
    return y;
}
__device__ __forceinline__ float rcp_approx(float x) {
    float y;
    asm("rcp.approx.ftz.f32 %0, %1;" : "=f"(y) : "f"(x));
    return y;
}

// ---------------------------------------------------------------------------
// Kernel 1: x' = (LayerNorm(ReLU(h @ W^T + b)) * gamma + beta) * sqrt(log2 e)
// 16 rows per 1024-thread block (128 blocks = one wave). W staged in SMEM
// with stride-65 padding (conflict-free per-thread sequential reads).
// ---------------------------------------------------------------------------
__global__ __launch_bounds__(1024) void mlp_ln_kernel(
    const float* __restrict__ h, const float* __restrict__ W,
    const float* __restrict__ bias, const float* __restrict__ gamma,
    const float* __restrict__ beta)
{
    __shared__ float Ws[C_DIM * 65];
    __shared__ float hs[16][C_DIM];
    __shared__ float red[16][2][2];   // [row][warp-half][sum, sumsq]

    const int tid = threadIdx.x;
    const int r   = tid >> 6;        // 0..15 row within block
    const int d   = tid & 63;        // output channel
    const int row = blockIdx.x * 16 + r;

    // Stage W (4096 floats) coalesced, padded layout Ws[d*65 + c].
    #pragma unroll
    for (int i = 0; i < 4; i++) {
        int idx = tid + i * 1024;
        Ws[(idx >> 6) * 65 + (idx & 63)] = W[idx];
    }
    hs[r][d] = h[row * C_DIM + d];
    __syncthreads();

    float acc = bias[d];
    #pragma unroll
    for (int c = 0; c < C_DIM; c++)
        acc = fmaf(hs[r][c], Ws[d * 65 + c], acc);

    float v = fmaxf(acc, 0.0f);

    // LayerNorm over the 64 channels of this row (= 2 warps).
    float s  = v;
    float s2 = v * v;
    #pragma unroll
    for (int off = 16; off; off >>= 1) {
        s  += __shfl_xor_sync(0xffffffffu, s,  off);
        s2 += __shfl_xor_sync(0xffffffffu, s2, off);
    }
    const int half = d >> 5;
    if ((d & 31) == 0) { red[r][half][0] = s; red[r][half][1] = s2; }
    __syncthreads();

    const float S   = red[r][0][0] + red[r][1][0];
    const float S2  = red[r][0][1] + red[r][1][1];
    const float mu  = S * (1.0f / 64.0f);
    const float var = S2 * (1.0f / 64.0f) - mu * mu;
    const float inv_std = rsqrtf(var + 1e-5f);

    g_x[row * C_DIM + d] =
        ((v - mu) * inv_std * gamma[d] + beta[d]) * SQRT_LOG2E;
}

// ---------------------------------------------------------------------------
// Kernel 2: out[b,i,j,c] = softmax_c( x[b,i,c] * x[b,j,c] )
//
// Exact R2-winning configuration (39.8us): 16x16 tile, 8-lane group per pair,
// full 8-iter unroll (deep per-warp store ILP beats occupancy here — proven
// by R3's regression when reg-clamped). Launched with PDL: blocks come up
// while kernel 1 drains; griddepcontrol.wait gates the g_x reads.
// ---------------------------------------------------------------------------
#define TI 16
#define TJ 16

__global__ __launch_bounds__(256) void pair_softmax_kernel(float* __restrict__ out)
{
    __shared__ float4 xi[TI * 16];   // 16 rows x 16 float4 = 4 KB
    __shared__ float4 xj[TJ * 16];

    const int bb = blockIdx.z;
    const int i0 = blockIdx.y * TI;
    const int j0 = blockIdx.x * TJ;
    const int tid = threadIdx.x;

    // PDL: wait for kernel 1's completion signal before touching g_x.
    asm volatile("griddepcontrol.wait;" ::: "memory");

    // Stage x tiles: each thread loads one float4 per tile.
    const float4* xg = (const float4*)g_x;   // row r = xg[r*16 + q]
    {
        const int r = tid >> 4;
        const int q = tid & 15;
        xi[tid] = xg[(size_t)(bb * N_DIM + i0 + r) * 16 + q];
        xj[tid] = xg[(size_t)(bb * N_DIM + j0 + r) * 16 + q];
    }
    __syncthreads();

    const int warp = tid >> 5;
    const int lane = tid & 31;
    const int p    = lane >> 3;   // which of 4 pairs this lane serves
    const int q    = lane & 7;    // channel float4 slot (and slot q+8)

    float4* out4 = (float4*)out;

    // xi rows for this warp (loop-invariant within each half).
    const float4* xi_lo = &xi[(2 * warp)     * 16];
    const float4* xi_hi = &xi[(2 * warp + 1) * 16];

    const size_t base_lo =
        ((size_t)(bb * N_DIM + i0 + 2 * warp) * N_DIM + (j0 + p)) * 16 + q;
    const size_t base_hi = base_lo + (size_t)N_DIM * 16;

    #pragma unroll
    for (int k = 0; k < 8; k++) {
        const int kk = k & 3;
        const float4* xrow = (k < 4) ? xi_lo : xi_hi;

        const float4 a0 = xrow[q];
        const float4 a1 = xrow[q + 8];
        const float4 b0 = xj[(4 * kk + p) * 16 + q];
        const float4 b1 = xj[(4 * kk + p) * 16 + q + 8];

        float e0 = ex2_approx(a0.x * b0.x);
        float e1 = ex2_approx(a0.y * b0.y);
        float e2 = ex2_approx(a0.z * b0.z);
        float e3 = ex2_approx(a0.w * b0.w);
        float e4 = ex2_approx(a1.x * b1.x);
        float e5 = ex2_approx(a1.y * b1.y);
        float e6 = ex2_approx(a1.z * b1.z);
        float e7 = ex2_approx(a1.w * b1.w);

        float s = ((e0 + e1) + (e2 + e3)) + ((e4 + e5) + (e6 + e7));
        s += __shfl_xor_sync(0xffffffffu, s, 4);
        s += __shfl_xor_sync(0xffffffffu, s, 2);
        s += __shfl_xor_sync(0xffffffffu, s, 1);

        const float inv = rcp_approx(s);

        float4 o0, o1;
        o0.x = e0 * inv; o0.y = e1 * inv; o0.z = e2 * inv; o0.w = e3 * inv;
        o1.x = e4 * inv; o1.y = e5 * inv; o1.z = e6 * inv; o1.w = e7 * inv;

        const size_t base = ((k < 4) ? base_lo : base_hi) + (size_t)kk * 64;
        __stcs(&out4[base],     o0);
        __stcs(&out4[base + 8], o1);
    }
}

// ---------------------------------------------------------------------------
extern "C" void kernel_launch(void* const* d_in, const int* in_sizes, int n_in,
                              void* d_out, int out_size)
{
    const float* h     = (const float*)d_in[0];
    const float* W     = (const float*)d_in[1];
    const float* bias  = (const float*)d_in[2];
    const float* gamma = (const float*)d_in[3];
    const float* beta  = (const float*)d_in[4];

    mlp_ln_kernel<<<NROWS / 16, 1024>>>(h, W, bias, gamma, beta);

    // Kernel 2 with programmatic dependent launch: overlap its launch/setup
    // with kernel 1's execution; griddepcontrol.wait inside the kernel
    // provides the data dependency on g_x.
    cudaLaunchConfig_t cfg = {};
    cfg.gridDim  = dim3(N_DIM / TJ, N_DIM / TI, B_DIM);   // (32, 32, 4)
    cfg.blockDim = dim3(256, 1, 1);
    cfg.dynamicSmemBytes = 0;
    cfg.stream = 0;

    cudaLaunchAttribute attrs[1];
    attrs[0].id = cudaLaunchAttributeProgrammaticStreamSerialization;
    attrs[0].val.programmaticStreamSerializationAllowed = 1;
    cfg.attrs = attrs;
    cfg.numAttrs = 1;

    cudaLaunchKernelEx(&cfg, pair_softmax_kernel, (float*)d_out);
}